// round 5
// baseline (speedup 1.0000x reference)
#include <cuda_runtime.h>
#include <cstdint>

#define UNITSN   64
#define GATES    256        // 4*UNITS
#define TSTEPS   100
#define FEAT     3
#define B_TOTAL  16384

#define CTA_THREADS    128
#define WARPS_PER_CTA  4
#define ROWS_PER_WARP  8
#define ROWS_PER_CTA   32
#define NUM_CTAS       (B_TOTAL / ROWS_PER_CTA)   // 512

// ---- shared memory layout (floats) ----
#define OFF_U    0            // 64*256      = 16384
#define OFF_W1   16384        // 64*64       = 4096
#define OFF_W    20480        // 3*256       = 768
#define OFF_B    21248        // 256
#define OFF_B1   21504        // 64
#define OFF_W2   21568        // 64*5        = 320
#define OFF_B2   21888        // 8 (padded)
#define OFF_H    21896        // 32 rows * 128 (duplicated h) = 4096
#define SMEM_FLOATS 25992
#define SMEM_BYTES  (SMEM_FLOATS * 4)   // 103968 B -> 2 CTAs/SM

// ---- scratch (device globals; no allocation) ----
__device__ int g_len[B_TOTAL];
__device__ int g_perm[B_TOTAL];
__device__ int g_bins[128];
__device__ int g_cursor[128];

// ---- f32x2 helpers ----
__device__ __forceinline__ unsigned long long fma2(unsigned long long a,
                                                   unsigned long long b,
                                                   unsigned long long c) {
    unsigned long long d;
    asm("fma.rn.f32x2 %0, %1, %2, %3;" : "=l"(d) : "l"(a), "l"(b), "l"(c));
    return d;
}
__device__ __forceinline__ unsigned long long dup2(float v) {
    unsigned long long d;
    asm("mov.b64 %0, {%1, %1};" : "=l"(d) : "f"(v));
    return d;
}
__device__ __forceinline__ float2 unpk(unsigned long long v) {
    float2 r;
    asm("mov.b64 {%0, %1}, %2;" : "=f"(r.x), "=f"(r.y) : "l"(v));
    return r;
}
__device__ __forceinline__ unsigned long long ld64(const float* p) {
    return *reinterpret_cast<const unsigned long long*>(p);
}
__device__ __forceinline__ float sigf(float x) {
    return __fdividef(1.0f, 1.0f + __expf(-x));
}
__device__ __forceinline__ float tanhfast(float x) {
    // tanh(x) = 1 - 2/(exp(2x)+1); saturates correctly at +-inf
    return 1.0f - __fdividef(2.0f, __expf(2.0f * x) + 1.0f);
}

// ============================ pre-pass kernels ============================

__global__ void k_init() {
    if (threadIdx.x < 128) g_bins[threadIdx.x] = 0;
}

// one warp per row: compute active length (last masked-true step + 1)
__global__ void k_len(const float* __restrict__ x) {
    int lane = threadIdx.x & 31;
    int wid  = threadIdx.x >> 5;
    int row  = blockIdx.x * 4 + wid;
    const float* p = x + (size_t)row * (TSTEPS * FEAT);

    auto chk = [&](int t) -> bool {
        return (p[t * 3] != 0.0f) | (p[t * 3 + 1] != 0.0f) | (p[t * 3 + 2] != 0.0f);
    };
    unsigned m0 = __ballot_sync(0xffffffffu, chk(lane));
    unsigned m1 = __ballot_sync(0xffffffffu, chk(lane + 32));
    unsigned m2 = __ballot_sync(0xffffffffu, chk(lane + 64));
    unsigned m3 = __ballot_sync(0xffffffffu, (lane + 96 < TSTEPS) ? chk(lane + 96) : false);

    if (lane == 0) {
        int len = 0;
        if      (m3) len = 96 + 32 - __clz(m3);
        else if (m2) len = 64 + 32 - __clz(m2);
        else if (m1) len = 32 + 32 - __clz(m1);
        else if (m0) len =      32 - __clz(m0);
        g_len[row] = len;
        atomicAdd(&g_bins[100 - len], 1);   // descending-length bins
    }
}

__global__ void k_prefix() {
    if (threadIdx.x == 0) {
        int run = 0;
        for (int k = 0; k <= 100; ++k) {
            g_cursor[k] = run;
            run += g_bins[k];
        }
    }
}

__global__ void k_scatter() {
    int row = blockIdx.x * blockDim.x + threadIdx.x;
    if (row < B_TOTAL) {
        int key = 100 - g_len[row];
        int pos = atomicAdd(&g_cursor[key], 1);
        g_perm[pos] = row;
    }
}

// ============================ main LSTM kernel ============================

__global__ __launch_bounds__(CTA_THREADS, 2)
void lstm_main(const float* __restrict__ x,  const float* __restrict__ W,
               const float* __restrict__ U,  const float* __restrict__ b,
               const float* __restrict__ W1, const float* __restrict__ b1,
               const float* __restrict__ W2, const float* __restrict__ b2,
               float* __restrict__ out) {
    extern __shared__ float sm[];
    int tid = threadIdx.x;

    // ---- cooperative smem staging ----
    for (int i = tid; i < 4096; i += CTA_THREADS)
        ((float4*)(sm + OFF_U))[i] = ((const float4*)U)[i];
    for (int i = tid; i < 1024; i += CTA_THREADS)
        ((float4*)(sm + OFF_W1))[i] = ((const float4*)W1)[i];
    for (int i = tid; i < 192; i += CTA_THREADS)
        ((float4*)(sm + OFF_W))[i] = ((const float4*)W)[i];
    for (int i = tid; i < 64; i += CTA_THREADS)
        ((float4*)(sm + OFF_B))[i] = ((const float4*)b)[i];
    for (int i = tid; i < 16; i += CTA_THREADS)
        ((float4*)(sm + OFF_B1))[i] = ((const float4*)b1)[i];
    for (int i = tid; i < 80; i += CTA_THREADS)
        ((float4*)(sm + OFF_W2))[i] = ((const float4*)W2)[i];
    if (tid < 8) sm[OFF_B2 + tid] = (tid < 5) ? b2[tid] : 0.0f;
    for (int i = tid; i < 1024; i += CTA_THREADS)
        ((float4*)(sm + OFF_H))[i] = make_float4(0.f, 0.f, 0.f, 0.f);
    __syncthreads();

    int lane = tid & 31;
    int wid  = tid >> 5;
    int slotBase = wid * ROWS_PER_WARP;                       // local row slot
    int grpBase  = blockIdx.x * ROWS_PER_CTA + slotBase;      // perm index base

    int rows[ROWS_PER_WARP];
    const float* xb[ROWS_PER_WARP];
    float* hp[ROWS_PER_WARP];
    int tmax = 0;
#pragma unroll
    for (int r = 0; r < ROWS_PER_WARP; ++r) {
        rows[r] = g_perm[grpBase + r];
        int l = g_len[rows[r]];
        tmax = max(tmax, l);
        xb[r] = x + (size_t)rows[r] * (TSTEPS * FEAT);
        hp[r] = sm + OFF_H + (slotBase + r) * 128;            // duplicated h row
    }

    // ---- hoist W pairs and b pairs into registers ----
    unsigned long long Wp[3][4], bp[4];
#pragma unroll
    for (int f = 0; f < 3; ++f)
#pragma unroll
        for (int q = 0; q < 4; ++q)
            Wp[f][q] = ld64(sm + OFF_W + f * GATES + q * UNITSN + 2 * lane);
#pragma unroll
    for (int q = 0; q < 4; ++q)
        bp[q] = ld64(sm + OFF_B + q * UNITSN + 2 * lane);

    float c0[ROWS_PER_WARP], c1[ROWS_PER_WARP];
#pragma unroll
    for (int r = 0; r < ROWS_PER_WARP; ++r) { c0[r] = 0.f; c1[r] = 0.f; }

    const float* Ubase = sm + OFF_U + 2 * lane;

    // ================= recurrence =================
    for (int t = 0; t < tmax; ++t) {
        float xv0[ROWS_PER_WARP], xv1[ROWS_PER_WARP], xv2[ROWS_PER_WARP];
        bool act[ROWS_PER_WARP];
        bool any = false;
#pragma unroll
        for (int r = 0; r < ROWS_PER_WARP; ++r) {
            const float* p = xb[r] + t * 3;
            xv0[r] = p[0]; xv1[r] = p[1]; xv2[r] = p[2];
            act[r] = (xv0[r] != 0.f) || (xv1[r] != 0.f) || (xv2[r] != 0.f);
            any = any || act[r];
        }
        if (!any) continue;   // uniform across warp

        unsigned long long z[ROWS_PER_WARP][4];
#pragma unroll
        for (int r = 0; r < ROWS_PER_WARP; ++r) {
            unsigned long long d0 = dup2(xv0[r]);
            unsigned long long d1 = dup2(xv1[r]);
            unsigned long long d2 = dup2(xv2[r]);
#pragma unroll
            for (int q = 0; q < 4; ++q) {
                unsigned long long a = fma2(d0, Wp[0][q], bp[q]);
                a = fma2(d1, Wp[1][q], a);
                z[r][q] = fma2(d2, Wp[2][q], a);
            }
        }

#pragma unroll 4
        for (int k = 0; k < UNITSN; k += 2) {
            const float* Uk = Ubase + k * GATES;
            unsigned long long u00 = ld64(Uk + 0);
            unsigned long long u01 = ld64(Uk + 64);
            unsigned long long u02 = ld64(Uk + 128);
            unsigned long long u03 = ld64(Uk + 192);
            unsigned long long u10 = ld64(Uk + 256);
            unsigned long long u11 = ld64(Uk + 320);
            unsigned long long u12 = ld64(Uk + 384);
            unsigned long long u13 = ld64(Uk + 448);
#pragma unroll
            for (int r = 0; r < ROWS_PER_WARP; ++r) {
                ulonglong2 hh = *reinterpret_cast<const ulonglong2*>(hp[r] + 2 * k);
                z[r][0] = fma2(hh.x, u00, z[r][0]);
                z[r][1] = fma2(hh.x, u01, z[r][1]);
                z[r][2] = fma2(hh.x, u02, z[r][2]);
                z[r][3] = fma2(hh.x, u03, z[r][3]);
                z[r][0] = fma2(hh.y, u10, z[r][0]);
                z[r][1] = fma2(hh.y, u11, z[r][1]);
                z[r][2] = fma2(hh.y, u12, z[r][2]);
                z[r][3] = fma2(hh.y, u13, z[r][3]);
            }
        }

        __syncwarp();   // all lanes done reading h before anyone rewrites it
#pragma unroll
        for (int r = 0; r < ROWS_PER_WARP; ++r) {
            if (act[r]) {
                float2 zi = unpk(z[r][0]);
                float2 zf = unpk(z[r][1]);
                float2 zg = unpk(z[r][2]);
                float2 zo = unpk(z[r][3]);
                float i0 = sigf(zi.x), f0 = sigf(zf.x), o0 = sigf(zo.x), g0 = tanhfast(zg.x);
                float i1 = sigf(zi.y), f1 = sigf(zf.y), o1 = sigf(zo.y), g1 = tanhfast(zg.y);
                c0[r] = f0 * c0[r] + i0 * g0;
                c1[r] = f1 * c1[r] + i1 * g1;
                float h0 = o0 * tanhfast(c0[r]);
                float h1 = o1 * tanhfast(c1[r]);
                *reinterpret_cast<float4*>(hp[r] + 4 * lane) =
                    make_float4(h0, h0, h1, h1);
            }
        }
        __syncwarp();   // writes visible before next step's reads
    }

    // ================= MLP head + softmax =================
    __syncwarp();
#pragma unroll 1
    for (int r = 0; r < ROWS_PER_WARP; ++r) {
        float* hr = hp[r];
        unsigned long long acc = ld64(sm + OFF_B1 + 2 * lane);
#pragma unroll 8
        for (int k = 0; k < UNITSN; ++k) {
            unsigned long long hd = ld64(hr + 2 * k);                      // (h[k],h[k])
            unsigned long long w  = ld64(sm + OFF_W1 + k * UNITSN + 2 * lane);
            acc = fma2(hd, w, acc);
        }
        float2 a = unpk(acc);
        float a0 = fmaxf(a.x, 0.f);
        float a1 = fmaxf(a.y, 0.f);
        __syncwarp();
        *reinterpret_cast<float4*>(hr + 4 * lane) = make_float4(a0, a0, a1, a1);
        __syncwarp();

        float logit = 0.0f;
        if (lane < 5) {
            logit = sm[OFF_B2 + lane];
#pragma unroll 8
            for (int k = 0; k < UNITSN; ++k)
                logit += hr[2 * k] * sm[OFF_W2 + k * 5 + lane];
        }
        float v[5];
#pragma unroll
        for (int j = 0; j < 5; ++j) v[j] = __shfl_sync(0xffffffffu, logit, j);
        float mx = v[0];
#pragma unroll
        for (int j = 1; j < 5; ++j) mx = fmaxf(mx, v[j]);
        float s = 0.0f;
#pragma unroll
        for (int j = 0; j < 5; ++j) { v[j] = __expf(v[j] - mx); s += v[j]; }
        if (lane < 5)
            out[(size_t)rows[r] * 5 + lane] = __fdividef(v[lane], s);
    }
}

// ============================ launch ============================

extern "C" void kernel_launch(void* const* d_in, const int* in_sizes, int n_in,
                              void* d_out, int out_size) {
    const float* x  = (const float*)d_in[0];
    const float* W  = (const float*)d_in[1];
    const float* U  = (const float*)d_in[2];
    const float* b  = (const float*)d_in[3];
    const float* W1 = (const float*)d_in[4];
    const float* b1 = (const float*)d_in[5];
    const float* W2 = (const float*)d_in[6];
    const float* b2 = (const float*)d_in[7];
    float* out = (float*)d_out;

    (void)in_sizes; (void)n_in; (void)out_size;

    // idempotent; ignore error if unsupported mid-capture (attribute persists)
    cudaFuncSetAttribute(lstm_main, cudaFuncAttributeMaxDynamicSharedMemorySize,
                         SMEM_BYTES);

    k_init   <<<1, 128>>>();
    k_len    <<<B_TOTAL / 4, 128>>>(x);
    k_prefix <<<1, 32>>>();
    k_scatter<<<B_TOTAL / 256, 256>>>();
    lstm_main<<<NUM_CTAS, CTA_THREADS, SMEM_BYTES>>>(x, W, U, b, W1, b1, W2, b2, out);
}